// round 1
// baseline (speedup 1.0000x reference)
#include <cuda_runtime.h>
#include <cstdint>

#define BATCH 16
#define HIDC  512
#define HW    64
#define PIX   (HW*HW)          /* 4096 */
#define NPIX  (BATCH*PIX)      /* 65536 */
#define FLAT  8320

// ---------------- scratch (static device globals: allocation-guard safe) ----
__device__ float g_act1[(size_t)BATCH*HIDC*PIX];   // 128 MiB
__device__ float g_act2[(size_t)BATCH*HIDC*PIX];   // 128 MiB
__device__ float g_feat[BATCH*FLAT];
__device__ float g_h1[BATCH*512];
__device__ float g_h2[BATCH*256];
__device__ float g_g1[BATCH*256];
__device__ float g_pm[BATCH*12];
__device__ float g_ls[BATCH*12];

// ---------------- conv + BN + ReLU as implicit GEMM ------------------------
// C[M=512, N=65536] = W[512, K=CIN*9] x im2col(X)[K, 65536]
// blocktile 128x128, ktile 8, 8x8 register microtile, reg-prefetch dbl buffer.
template<int CIN>
__global__ __launch_bounds__(256, 2)
void conv_bn_relu_kernel(const float* __restrict__ in,
                         const float* __restrict__ w,
                         const float* __restrict__ cbias,
                         const float* __restrict__ bng, const float* __restrict__ bnb,
                         const float* __restrict__ bnm, const float* __restrict__ bnv,
                         float* __restrict__ out)
{
    constexpr int K   = CIN * 9;
    constexpr int NKT = K / 8;

    __shared__ float As[8][128];   // As[k][m]
    __shared__ float Bs[8][128];   // Bs[k][n]

    const int t    = threadIdx.x;
    const int col0 = blockIdx.x * 128;   // pixel tile base (0..65535)
    const int m0   = blockIdx.y * 128;   // output-channel tile base

    const int bn = col0 >> 12;           // image index (4096 px / image, 128 | 4096)
    const int h0 = (col0 & 4095) >> 6;   // base row (block spans rows h0, h0+1)

    // A-tile load indices: 128 m x 8 k, thread loads float4 along k
    const int ma  = t >> 1;
    const int kqa = (t & 1) * 4;
    // B-tile load indices: 8 k x 128 n, thread loads 4 consecutive n
    const int kb = t >> 5;
    const int n4 = (t & 31) * 4;
    const int hB = h0 + (n4 >> 6);       // row for this thread's 4 pixels
    const int wB = n4 & 63;

    const float* inImg = in + (size_t)bn * CIN * PIX;

    const int tn = (t & 15) * 8;         // microtile n base
    const int tm = (t >> 4) * 8;         // microtile m base

    float acc[8][8];
    #pragma unroll
    for (int i = 0; i < 8; i++)
        #pragma unroll
        for (int j = 0; j < 8; j++) acc[i][j] = 0.f;

    float4 rA;
    float4 rB;

    auto fetch = [&](int kt) {
        const int k0 = kt * 8;
        rA = *reinterpret_cast<const float4*>(&w[(size_t)(m0 + ma) * K + k0 + kqa]);
        const int kg  = k0 + kb;
        const int cin = kg / 9;
        const int r   = kg - cin * 9;
        const int r3  = r / 3;
        const int dh  = r3 - 1;
        const int dw  = (r - r3 * 3) - 1;
        const int hh  = hB + dh;
        const bool rowok = ((unsigned)hh < (unsigned)HW);
        const float* rowp = inImg + ((size_t)cin * HW + hh) * HW;
        float v[4];
        #pragma unroll
        for (int j = 0; j < 4; j++) {
            const int ww = wB + j + dw;
            v[j] = (rowok && (unsigned)ww < (unsigned)HW) ? rowp[ww] : 0.f;
        }
        rB = make_float4(v[0], v[1], v[2], v[3]);
    };
    auto stage = [&]() {
        As[kqa + 0][ma] = rA.x;
        As[kqa + 1][ma] = rA.y;
        As[kqa + 2][ma] = rA.z;
        As[kqa + 3][ma] = rA.w;
        *reinterpret_cast<float4*>(&Bs[kb][n4]) = rB;
    };

    fetch(0); stage();
    __syncthreads();

    for (int kt = 0; kt < NKT; ++kt) {
        if (kt + 1 < NKT) fetch(kt + 1);   // gmem prefetch overlapped w/ compute
        #pragma unroll
        for (int kk = 0; kk < 8; ++kk) {
            float4 a0 = *reinterpret_cast<const float4*>(&As[kk][tm]);
            float4 a1 = *reinterpret_cast<const float4*>(&As[kk][tm + 4]);
            float4 b0 = *reinterpret_cast<const float4*>(&Bs[kk][tn]);
            float4 b1 = *reinterpret_cast<const float4*>(&Bs[kk][tn + 4]);
            float av[8] = {a0.x, a0.y, a0.z, a0.w, a1.x, a1.y, a1.z, a1.w};
            float bv[8] = {b0.x, b0.y, b0.z, b0.w, b1.x, b1.y, b1.z, b1.w};
            #pragma unroll
            for (int i = 0; i < 8; i++)
                #pragma unroll
                for (int j = 0; j < 8; j++)
                    acc[i][j] = fmaf(av[i], bv[j], acc[i][j]);
        }
        __syncthreads();
        if (kt + 1 < NKT) { stage(); __syncthreads(); }
    }

    // Fused BN + ReLU epilogue: y = relu(acc*scale + shift)
    #pragma unroll
    for (int i = 0; i < 8; i++) {
        const int oc = m0 + tm + i;
        const float s  = bng[oc] * rsqrtf(bnv[oc] + 1e-5f);
        const float sh = (cbias[oc] - bnm[oc]) * s + bnb[oc];
        float* orow = out + ((size_t)bn * HIDC + oc) * PIX + (col0 & 4095) + tn;
        float4 v0, v1;
        v0.x = fmaxf(fmaf(acc[i][0], s, sh), 0.f);
        v0.y = fmaxf(fmaf(acc[i][1], s, sh), 0.f);
        v0.z = fmaxf(fmaf(acc[i][2], s, sh), 0.f);
        v0.w = fmaxf(fmaf(acc[i][3], s, sh), 0.f);
        v1.x = fmaxf(fmaf(acc[i][4], s, sh), 0.f);
        v1.y = fmaxf(fmaf(acc[i][5], s, sh), 0.f);
        v1.z = fmaxf(fmaf(acc[i][6], s, sh), 0.f);
        v1.w = fmaxf(fmaf(acc[i][7], s, sh), 0.f);
        *reinterpret_cast<float4*>(&orow[0]) = v0;
        *reinterpret_cast<float4*>(&orow[4]) = v1;
    }
}

// ---------------- adaptive avg pool 64x64 -> 4x4 (deterministic) ------------
__global__ void pool_kernel(float* __restrict__ feat)
{
    const int nc = blockIdx.x;            // 0..8191
    const int n  = nc >> 9;
    const int c  = nc & 511;
    const float* p = g_act2 + (size_t)nc * PIX;

    const int t  = threadIdx.x;           // 256
    const int q  = t >> 4;                // window 0..15
    const int r  = t & 15;                // row within window
    const int qh = q >> 2, qw = q & 3;
    const float* row = p + (qh * 16 + r) * HW + qw * 16;
    float s = 0.f;
    #pragma unroll
    for (int j = 0; j < 16; j++) s += row[j];

    __shared__ float part[256];
    part[t] = s;
    __syncthreads();
    if (t < 16) {
        float acc = 0.f;
        #pragma unroll
        for (int j = 0; j < 16; j++) acc += part[t * 16 + j];
        feat[n * FLAT + c * 16 + t] = acc * (1.f / 256.f);
    }
}

// ---------------- clinical embedding (4 -> 128) -----------------------------
__global__ void clin_kernel(const float* __restrict__ x,
                            const float* __restrict__ w,
                            const float* __restrict__ b,
                            float* __restrict__ feat)
{
    const int n = blockIdx.x;
    const int j = threadIdx.x;    // 128
    float s = b[j];
    #pragma unroll
    for (int i = 0; i < 4; i++) s = fmaf(w[j * 4 + i], x[n * 4 + i], s);
    feat[n * FLAT + 8192 + j] = s;
}

// ---------------- generic linear: warp per (n, o) dot product ---------------
// act: 1=relu, 2=sigmoid, 3=clip[-5,0]
__global__ void linear_kernel(const float* __restrict__ in,
                              const float* __restrict__ w,
                              const float* __restrict__ b,
                              float* __restrict__ out,
                              int In, int Out, int act)
{
    const int gw   = (blockIdx.x * blockDim.x + threadIdx.x) >> 5;
    const int lane = threadIdx.x & 31;
    if (gw >= 16 * Out) return;
    const int o = gw >> 4;      // 16 consecutive warps share a weight row
    const int n = gw & 15;
    const float* wr = w + (size_t)o * In;
    const float* xr = in + (size_t)n * In;
    float s = 0.f;
    for (int i = lane; i < In; i += 32) s = fmaf(wr[i], xr[i], s);
    #pragma unroll
    for (int off = 16; off; off >>= 1) s += __shfl_xor_sync(0xFFFFFFFFu, s, off);
    if (lane == 0) {
        s += b[o];
        if (act == 1)      s = fmaxf(s, 0.f);
        else if (act == 2) s = 1.f / (1.f + expf(-s));
        else if (act == 3) s = fminf(fmaxf(s, -5.f), 0.f);
        out[n * Out + o] = s;
    }
}

// ---------------- sampling head --------------------------------------------
// out layout: coords[16*15*2] | log_probs[16*3] | patches[16*3*4]
__global__ void head_kernel(const float* __restrict__ noise,
                            const float* __restrict__ u,
                            float* __restrict__ out)
{
    const int t = threadIdx.x;
    if (t >= 48) return;
    const int n = t / 3, k = t % 3;
    const int nk = n * 3 + k;

    float pm[4], ls[4], p[4];
    float lp = 0.f;
    #pragma unroll
    for (int j = 0; j < 4; j++) {
        pm[j] = g_pm[n * 12 + k * 4 + j];
        ls[j] = g_ls[n * 12 + k * 4 + j];
        const float sd = expf(ls[j]);
        p[j] = pm[j] + noise[nk * 4 + j] * sd;
        const float z = (p[j] - pm[j]) / sd;
        lp += z * z + 2.f * ls[j];
    }
    lp *= -0.5f;
    #pragma unroll
    for (int j = 0; j < 4; j++) p[j] = fminf(fmaxf(p[j], 0.f), 1.f);

    const float cx = p[0], cy = p[1];
    const float s2 = p[2] * 0.2f + 0.1f;
    const float s3 = p[3] * 0.2f + 0.1f;

    out[480 + nk] = lp;
    out[528 + nk * 4 + 0] = cx;
    out[528 + nk * 4 + 1] = cy;
    out[528 + nk * 4 + 2] = s2;
    out[528 + nk * 4 + 3] = s3;

    #pragma unroll
    for (int pt = 0; pt < 5; pt++) {
        const float ux = u[(nk * 5 + pt) * 2 + 0];
        const float uy = u[(nk * 5 + pt) * 2 + 1];
        float px = (cx + (ux - 0.5f) * s2) * 256.f;
        float py = (cy + (uy - 0.5f) * s3) * 256.f;
        px = fminf(fmaxf(px, 0.f), 255.f);
        py = fminf(fmaxf(py, 0.f), 255.f);
        out[(n * 15 + k * 5 + pt) * 2 + 0] = px;
        out[(n * 15 + k * 5 + pt) * 2 + 1] = py;
    }
}

// ---------------- launcher ---------------------------------------------------
extern "C" void kernel_launch(void* const* d_in, const int* in_sizes, int n_in,
                              void* d_out, int out_size)
{
    const float* img   = (const float*)d_in[0];
    const float* clin  = (const float*)d_in[1];
    const float* noise = (const float*)d_in[2];
    const float* u     = (const float*)d_in[3];
    const float* c1w = (const float*)d_in[4];
    const float* c1b = (const float*)d_in[5];
    const float* b1g = (const float*)d_in[6];
    const float* b1b = (const float*)d_in[7];
    const float* b1m = (const float*)d_in[8];
    const float* b1v = (const float*)d_in[9];
    const float* c2w = (const float*)d_in[10];
    const float* c2b = (const float*)d_in[11];
    const float* b2g = (const float*)d_in[12];
    const float* b2b = (const float*)d_in[13];
    const float* b2m = (const float*)d_in[14];
    const float* b2v = (const float*)d_in[15];
    const float* clw = (const float*)d_in[16];
    const float* clb = (const float*)d_in[17];
    const float* p1w = (const float*)d_in[18];
    const float* p1b = (const float*)d_in[19];
    const float* p2w = (const float*)d_in[20];
    const float* p2b = (const float*)d_in[21];
    const float* p3w = (const float*)d_in[22];
    const float* p3b = (const float*)d_in[23];
    const float* l1w = (const float*)d_in[24];
    const float* l1b = (const float*)d_in[25];
    const float* l2w = (const float*)d_in[26];
    const float* l2b = (const float*)d_in[27];

    float *act1, *act2, *feat, *h1, *h2, *g1, *pm, *ls;
    cudaGetSymbolAddress((void**)&act1, g_act1);
    cudaGetSymbolAddress((void**)&act2, g_act2);
    cudaGetSymbolAddress((void**)&feat, g_feat);
    cudaGetSymbolAddress((void**)&h1,   g_h1);
    cudaGetSymbolAddress((void**)&h2,   g_h2);
    cudaGetSymbolAddress((void**)&g1,   g_g1);
    cudaGetSymbolAddress((void**)&pm,   g_pm);
    cudaGetSymbolAddress((void**)&ls,   g_ls);

    const dim3 cgrid(NPIX / 128, HIDC / 128);   // (512, 4)
    conv_bn_relu_kernel<256><<<cgrid, 256>>>(img,  c1w, c1b, b1g, b1b, b1m, b1v, act1);
    conv_bn_relu_kernel<512><<<cgrid, 256>>>(act1, c2w, c2b, b2g, b2b, b2m, b2v, act2);

    pool_kernel<<<BATCH * HIDC, 256>>>(feat);
    clin_kernel<<<BATCH, 128>>>(clin, clw, clb, feat);

    // warp-per-output linears: blocks = ceil(16*Out / 8 warps)
    linear_kernel<<<(16 * 512 + 7) / 8, 256>>>(feat, p1w, p1b, h1, FLAT, 512, 1);
    linear_kernel<<<(16 * 256 + 7) / 8, 256>>>(h1,   p2w, p2b, h2, 512,  256, 1);
    linear_kernel<<<(16 * 12  + 7) / 8, 256>>>(h2,   p3w, p3b, pm, 256,  12,  2);
    linear_kernel<<<(16 * 256 + 7) / 8, 256>>>(feat, l1w, l1b, g1, FLAT, 256, 1);
    linear_kernel<<<(16 * 12  + 7) / 8, 256>>>(g1,   l2w, l2b, ls, 256,  12,  3);

    head_kernel<<<1, 64>>>(noise, u, (float*)d_out);
}

// round 5
// speedup vs baseline: 2.9632x; 2.9632x over previous
#include <cuda_runtime.h>
#include <cstdint>

// R5 = resubmit of R4 design (infra 'container failed twice' x1 on this code;
// R3 proved compile errors are reported verbatim, so this code never ran).

#define BATCH 16
#define HIDC  512
#define HW    64
#define PIX   4096
#define NPIX  65536
#define FLAT  8320

// ---------------- scratch (static device globals) ---------------------------
__device__ float g_act1[(size_t)BATCH*HIDC*PIX];   // 128 MiB
__device__ float g_act2[(size_t)BATCH*HIDC*PIX];   // 128 MiB
__device__ float g_feat[BATCH*FLAT];
__device__ float g_h1[BATCH*512];
__device__ float g_h2[BATCH*256];
__device__ float g_g1[BATCH*256];
__device__ float g_pm[BATCH*12];
__device__ float g_ls[BATCH*12];

// ---------------- helpers ----------------------------------------------------
__device__ __forceinline__ uint32_t f2tf32(float f) {
    uint32_t r;
    asm("cvt.rna.tf32.f32 %0, %1;" : "=r"(r) : "f"(f));
    return r;
}
__device__ __forceinline__ void mma_tf32(float* c, const uint32_t* a, const uint32_t* b) {
    asm volatile(
        "mma.sync.aligned.m16n8k8.row.col.f32.tf32.tf32.f32 "
        "{%0,%1,%2,%3}, {%4,%5,%6,%7}, {%8,%9}, {%0,%1,%2,%3};"
        : "+f"(c[0]), "+f"(c[1]), "+f"(c[2]), "+f"(c[3])
        : "r"(a[0]), "r"(a[1]), "r"(a[2]), "r"(a[3]), "r"(b[0]), "r"(b[1]));
}

// ---------------- mma.sync tf32 implicit-GEMM conv + BN + ReLU --------------
// GEMM: C[512 oc, 65536 px] = W[512, K] x im2col[K, 65536], K = CIN*9.
// CTA tile 128(M) x 256(N), K-chunk 16. 8 warps = 2(M) x 4(N), warp tile 64x64.
// SMEM rows padded to 20 words: frag-LDS bank pattern (m*20)%32 is conflict-free.
template<int CIN>
__global__ __launch_bounds__(256, 1)
void conv_mma(const float* __restrict__ in, const float* __restrict__ w,
              const float* __restrict__ cbias,
              const float* __restrict__ bng, const float* __restrict__ bnb,
              const float* __restrict__ bnm, const float* __restrict__ bnv,
              float* __restrict__ out)
{
    constexpr int K   = CIN * 9;
    constexpr int NKT = K / 16;

    extern __shared__ uint32_t sm[];
    constexpr int AS0 = 0;          // A: [128][20]
    constexpr int AS1 = 2560;
    constexpr int BS0 = 5120;       // B: [256][20]
    constexpr int BS1 = 10240;
    constexpr int TAB = 15360;      // im2col table: K ints

    const int t    = threadIdx.x;
    const int wid  = t >> 5;
    const int lane = t & 31;
    const int g    = lane >> 2;     // groupID (row within fragment)
    const int tig  = lane & 3;      // thread-in-group (col within fragment)
    const int warp_m = (wid >> 2) * 64;
    const int warp_n = (wid & 3) * 64;

    const int m0    = blockIdx.x * 128;
    const int pix0  = blockIdx.y * 256;
    const int bn    = pix0 >> 12;
    const int lpix0 = pix0 & 4095;

    // im2col offset table: (elem_off+65) | (tap r << 21); max 511*4096+130 < 2^21.
    for (int k = t; k < K; k += 256) {
        const int cin = k / 9;
        const int r   = k - cin * 9;
        const int dh  = r / 3 - 1;
        const int dw  = r - (r / 3) * 3 - 1;
        ((int*)(sm + TAB))[k] = ((cin * PIX + dh * HW + dw) + 65) | (r << 21);
    }
    __syncthreads();

    // B-gather: thread t owns pixel n = t (tile = 4 image rows)
    const int hh = (lpix0 >> 6) + (t >> 6);
    const int ww = t & 63;
    const float* pTh = in + (size_t)bn * CIN * PIX + hh * HW + ww;
    unsigned msk = 0;
    #pragma unroll
    for (int r = 0; r < 9; r++) {
        const int dh = r / 3 - 1, dw = r % 3 - 1;
        if ((unsigned)(hh + dh) < (unsigned)HW && (unsigned)(ww + dw) < (unsigned)HW)
            msk |= 1u << r;
    }

    // A-load: thread t owns weight row m = t>>1, k-half (t&1)*8
    const int am = t >> 1;
    const int ak = (t & 1) * 8;
    const float* wp = w + (size_t)(m0 + am) * K + ak;

    float4 rA0, rA1;
    float  rB[16];

    auto fetch = [&](int kt) {
        const int k0 = kt * 16;
        rA0 = __ldg((const float4*)(wp + k0));
        rA1 = __ldg((const float4*)(wp + k0 + 4));
        const int* tab = (const int*)(sm + TAB) + k0;
        #pragma unroll
        for (int j = 0; j < 16; j++) {
            const int e   = tab[j];
            const int r   = e >> 21;
            const int off = (e & 0x1FFFFF) - 65;
            rB[j] = ((msk >> r) & 1u) ? __ldg(pTh + off) : 0.f;
        }
    };
    auto stage = [&](int buf) {
        uint32_t* As = sm + (buf ? AS1 : AS0) + am * 20 + ak;
        As[0] = f2tf32(rA0.x); As[1] = f2tf32(rA0.y);
        As[2] = f2tf32(rA0.z); As[3] = f2tf32(rA0.w);
        As[4] = f2tf32(rA1.x); As[5] = f2tf32(rA1.y);
        As[6] = f2tf32(rA1.z); As[7] = f2tf32(rA1.w);
        uint32_t* Bs = sm + (buf ? BS1 : BS0) + t * 20;
        #pragma unroll
        for (int j = 0; j < 16; j++) Bs[j] = f2tf32(rB[j]);
    };

    float c[4][8][4];
    #pragma unroll
    for (int mf = 0; mf < 4; mf++)
        #pragma unroll
        for (int nf = 0; nf < 8; nf++)
            #pragma unroll
            for (int i = 0; i < 4; i++) c[mf][nf][i] = 0.f;

    fetch(0);
    stage(0);
    __syncthreads();

    for (int kt = 0; kt < NKT; ++kt) {
        if (kt + 1 < NKT) fetch(kt + 1);

        const uint32_t* As = sm + ((kt & 1) ? AS1 : AS0);
        const uint32_t* Bs = sm + ((kt & 1) ? BS1 : BS0);
        #pragma unroll
        for (int s = 0; s < 2; ++s) {
            uint32_t a[4][4], b[8][2];
            #pragma unroll
            for (int mf = 0; mf < 4; mf++) {
                const uint32_t* ap = As + (warp_m + mf * 16 + g) * 20 + s * 8 + tig;
                a[mf][0] = ap[0];
                a[mf][1] = ap[8 * 20];
                a[mf][2] = ap[4];
                a[mf][3] = ap[8 * 20 + 4];
            }
            #pragma unroll
            for (int nf = 0; nf < 8; nf++) {
                const uint32_t* bp = Bs + (warp_n + nf * 8 + g) * 20 + s * 8 + tig;
                b[nf][0] = bp[0];
                b[nf][1] = bp[4];
            }
            #pragma unroll
            for (int mf = 0; mf < 4; mf++)
                #pragma unroll
                for (int nf = 0; nf < 8; nf++)
                    mma_tf32(c[mf][nf], a[mf], b[nf]);
        }

        if (kt + 1 < NKT) stage((kt + 1) & 1);
        __syncthreads();
    }

    // ---- epilogue: BN + ReLU, direct to gmem --------------------------------
    #pragma unroll
    for (int mf = 0; mf < 4; mf++) {
        const int r0  = warp_m + mf * 16 + g;
        const int oc0 = m0 + r0;
        const int oc1 = oc0 + 8;
        const float s0  = bng[oc0] * rsqrtf(bnv[oc0] + 1e-5f);
        const float sh0 = (cbias[oc0] - bnm[oc0]) * s0 + bnb[oc0];
        const float s1  = bng[oc1] * rsqrtf(bnv[oc1] + 1e-5f);
        const float sh1 = (cbias[oc1] - bnm[oc1]) * s1 + bnb[oc1];
        float* o0 = out + ((size_t)(bn * HIDC + oc0)) * PIX + lpix0;
        float* o1 = o0 + 8 * PIX;
        #pragma unroll
        for (int nf = 0; nf < 8; nf++) {
            const int col = warp_n + nf * 8 + 2 * tig;
            float2 v0, v1;
            v0.x = fmaxf(fmaf(c[mf][nf][0], s0, sh0), 0.f);
            v0.y = fmaxf(fmaf(c[mf][nf][1], s0, sh0), 0.f);
            v1.x = fmaxf(fmaf(c[mf][nf][2], s1, sh1), 0.f);
            v1.y = fmaxf(fmaf(c[mf][nf][3], s1, sh1), 0.f);
            *(float2*)(o0 + col) = v0;
            *(float2*)(o1 + col) = v1;
        }
    }
}

// ---------------- adaptive avg pool 64x64 -> 4x4 ----------------------------
__global__ void pool_kernel(float* __restrict__ feat)
{
    const int nc = blockIdx.x;
    const int n  = nc >> 9;
    const int c  = nc & 511;
    const float* p = g_act2 + (size_t)nc * PIX;
    const int t = threadIdx.x;
    const int q = t >> 4, r = t & 15;
    const int qh = q >> 2, qw = q & 3;
    const float* row = p + (qh * 16 + r) * HW + qw * 16;
    float s = 0.f;
    #pragma unroll
    for (int j = 0; j < 16; j++) s += row[j];
    __shared__ float part[256];
    part[t] = s;
    __syncthreads();
    if (t < 16) {
        float acc = 0.f;
        #pragma unroll
        for (int j = 0; j < 16; j++) acc += part[t * 16 + j];
        feat[n * FLAT + c * 16 + t] = acc * (1.f / 256.f);
    }
}

// ---------------- clinical embedding (4 -> 128) -----------------------------
__global__ void clin_kernel(const float* __restrict__ x, const float* __restrict__ w,
                            const float* __restrict__ b, float* __restrict__ feat)
{
    const int n = blockIdx.x;
    const int j = threadIdx.x;
    float s = b[j];
    #pragma unroll
    for (int i = 0; i < 4; i++) s = fmaf(w[j * 4 + i], x[n * 4 + i], s);
    feat[n * FLAT + 8192 + j] = s;
}

// ---------------- generic linear: warp per (n, o) ---------------------------
__global__ void linear_kernel(const float* __restrict__ in, const float* __restrict__ w,
                              const float* __restrict__ b, float* __restrict__ out,
                              int In, int Out, int act)
{
    const int gw   = (blockIdx.x * blockDim.x + threadIdx.x) >> 5;
    const int lane = threadIdx.x & 31;
    if (gw >= 16 * Out) return;
    const int o = gw >> 4;
    const int n = gw & 15;
    const float* wr = w + (size_t)o * In;
    const float* xr = in + (size_t)n * In;
    float s = 0.f;
    for (int i = lane; i < In; i += 32) s = fmaf(wr[i], xr[i], s);
    #pragma unroll
    for (int off = 16; off; off >>= 1) s += __shfl_xor_sync(0xFFFFFFFFu, s, off);
    if (lane == 0) {
        s += b[o];
        if (act == 1)      s = fmaxf(s, 0.f);
        else if (act == 2) s = 1.f / (1.f + expf(-s));
        else if (act == 3) s = fminf(fmaxf(s, -5.f), 0.f);
        out[n * Out + o] = s;
    }
}

// ---------------- sampling head ---------------------------------------------
__global__ void head_kernel(const float* __restrict__ noise, const float* __restrict__ u,
                            float* __restrict__ out)
{
    const int t = threadIdx.x;
    if (t >= 48) return;
    const int n = t / 3, k = t % 3;
    const int nk = n * 3 + k;
    float pm[4], ls[4], p[4];
    float lp = 0.f;
    #pragma unroll
    for (int j = 0; j < 4; j++) {
        pm[j] = g_pm[n * 12 + k * 4 + j];
        ls[j] = g_ls[n * 12 + k * 4 + j];
        const float sd = expf(ls[j]);
        p[j] = pm[j] + noise[nk * 4 + j] * sd;
        const float z = (p[j] - pm[j]) / sd;
        lp += z * z + 2.f * ls[j];
    }
    lp *= -0.5f;
    #pragma unroll
    for (int j = 0; j < 4; j++) p[j] = fminf(fmaxf(p[j], 0.f), 1.f);
    const float cx = p[0], cy = p[1];
    const float s2 = p[2] * 0.2f + 0.1f;
    const float s3 = p[3] * 0.2f + 0.1f;
    out[480 + nk] = lp;
    out[528 + nk * 4 + 0] = cx;
    out[528 + nk * 4 + 1] = cy;
    out[528 + nk * 4 + 2] = s2;
    out[528 + nk * 4 + 3] = s3;
    #pragma unroll
    for (int pt = 0; pt < 5; pt++) {
        const float ux = u[(nk * 5 + pt) * 2 + 0];
        const float uy = u[(nk * 5 + pt) * 2 + 1];
        float px = (cx + (ux - 0.5f) * s2) * 256.f;
        float py = (cy + (uy - 0.5f) * s3) * 256.f;
        px = fminf(fmaxf(px, 0.f), 255.f);
        py = fminf(fmaxf(py, 0.f), 255.f);
        out[(n * 15 + k * 5 + pt) * 2 + 0] = px;
        out[(n * 15 + k * 5 + pt) * 2 + 1] = py;
    }
}

// ---------------- launcher ---------------------------------------------------
extern "C" void kernel_launch(void* const* d_in, const int* in_sizes, int n_in,
                              void* d_out, int out_size)
{
    const float* img   = (const float*)d_in[0];
    const float* clin  = (const float*)d_in[1];
    const float* noise = (const float*)d_in[2];
    const float* u     = (const float*)d_in[3];
    const float* c1w = (const float*)d_in[4];
    const float* c1b = (const float*)d_in[5];
    const float* b1g = (const float*)d_in[6];
    const float* b1b = (const float*)d_in[7];
    const float* b1m = (const float*)d_in[8];
    const float* b1v = (const float*)d_in[9];
    const float* c2w = (const float*)d_in[10];
    const float* c2b = (const float*)d_in[11];
    const float* b2g = (const float*)d_in[12];
    const float* b2b = (const float*)d_in[13];
    const float* b2m = (const float*)d_in[14];
    const float* b2v = (const float*)d_in[15];
    const float* clw = (const float*)d_in[16];
    const float* clb = (const float*)d_in[17];
    const float* p1w = (const float*)d_in[18];
    const float* p1b = (const float*)d_in[19];
    const float* p2w = (const float*)d_in[20];
    const float* p2b = (const float*)d_in[21];
    const float* p3w = (const float*)d_in[22];
    const float* p3b = (const float*)d_in[23];
    const float* l1w = (const float*)d_in[24];
    const float* l1b = (const float*)d_in[25];
    const float* l2w = (const float*)d_in[26];
    const float* l2b = (const float*)d_in[27];

    float *act1, *act2, *feat, *h1, *h2, *g1, *pm, *ls;
    cudaGetSymbolAddress((void**)&act1, g_act1);
    cudaGetSymbolAddress((void**)&act2, g_act2);
    cudaGetSymbolAddress((void**)&feat, g_feat);
    cudaGetSymbolAddress((void**)&h1,   g_h1);
    cudaGetSymbolAddress((void**)&h2,   g_h2);
    cudaGetSymbolAddress((void**)&g1,   g_g1);
    cudaGetSymbolAddress((void**)&pm,   g_pm);
    cudaGetSymbolAddress((void**)&ls,   g_ls);

    const int smem1 = 15360 * 4 + 2304 * 4;   // 70656 B
    const int smem2 = 15360 * 4 + 4608 * 4;   // 79872 B
    cudaFuncSetAttribute(conv_mma<256>, cudaFuncAttributeMaxDynamicSharedMemorySize, smem1);
    cudaFuncSetAttribute(conv_mma<512>, cudaFuncAttributeMaxDynamicSharedMemorySize, smem2);

    const dim3 cgrid(HIDC / 128, NPIX / 256);   // (4, 256)
    conv_mma<256><<<cgrid, 256, smem1>>>(img,  c1w, c1b, b1g, b1b, b1m, b1v, act1);
    conv_mma<512><<<cgrid, 256, smem2>>>(act1, c2w, c2b, b2g, b2b, b2m, b2v, act2);

    pool_kernel<<<BATCH * HIDC, 256>>>(feat);
    clin_kernel<<<BATCH, 128>>>(clin, clw, clb, feat);

    linear_kernel<<<(16 * 512 + 7) / 8, 256>>>(feat, p1w, p1b, h1, FLAT, 512, 1);
    linear_kernel<<<(16 * 256 + 7) / 8, 256>>>(h1,   p2w, p2b, h2, 512,  256, 1);
    linear_kernel<<<(16 * 12  + 7) / 8, 256>>>(h2,   p3w, p3b, pm, 256,  12,  2);
    linear_kernel<<<(16 * 256 + 7) / 8, 256>>>(feat, l1w, l1b, g1, FLAT, 256, 1);
    linear_kernel<<<(16 * 12  + 7) / 8, 256>>>(g1,   l2w, l2b, ls, 256,  12,  3);

    head_kernel<<<1, 64>>>(noise, u, (float*)d_out);
}

// round 7
// speedup vs baseline: 3.4424x; 1.1617x over previous
#include <cuda_runtime.h>
#include <cuda_fp16.h>
#include <cstdint>

// R7 = resubmit of R6 fp16 design. R6's 'container failed twice' is infra:
// identical code failed in R4 and passed in R5; failures alternate by round
// and never carry compile/runtime output. This code has not yet executed.

#define BATCH 16
#define HIDC  512
#define HW    64
#define PIX   4096
#define NPIX  65536
#define FLAT  8320

// ---------------- scratch (static device globals) ---------------------------
__device__ float g_act1[(size_t)BATCH*HIDC*PIX];   // 128 MiB
__device__ float g_act2[(size_t)BATCH*HIDC*PIX];   // 128 MiB
__device__ float g_feat[BATCH*FLAT];
__device__ float g_h1[BATCH*512];
__device__ float g_h2[BATCH*256];
__device__ float g_g1[BATCH*256];
__device__ float g_pm[BATCH*12];
__device__ float g_ls[BATCH*12];

// ---------------- helpers ----------------------------------------------------
__device__ __forceinline__ uint32_t h2pack(float lo, float hi) {
    __half2 h = __floats2half2_rn(lo, hi);   // .x = lo half of the b32 reg
    return *reinterpret_cast<uint32_t*>(&h);
}
__device__ __forceinline__ void mma_f16(float* c, const uint32_t* a, const uint32_t* b) {
    asm volatile(
        "mma.sync.aligned.m16n8k16.row.col.f32.f16.f16.f32 "
        "{%0,%1,%2,%3}, {%4,%5,%6,%7}, {%8,%9}, {%0,%1,%2,%3};"
        : "+f"(c[0]), "+f"(c[1]), "+f"(c[2]), "+f"(c[3])
        : "r"(a[0]), "r"(a[1]), "r"(a[2]), "r"(a[3]), "r"(b[0]), "r"(b[1]));
}

// ---------------- mma.sync fp16 implicit-GEMM conv + BN + ReLU --------------
// GEMM: C[512 oc, 65536 px] = W[512, K] x im2col[K, 65536], K = CIN*9.
// CTA tile 128(M) x 256(N), K-chunk 16 (one k16 MMA step). 8 warps = 2x4,
// warp tile 64x64 -> 32 MMAs/warp/chunk (half of the tf32 version).
// SMEM tiles stored as half2 words, row stride 12 words: frag-LDS bank
// pattern (12g+tig)%32 covers all 32 banks (conflict-free).
template<int CIN>
__global__ __launch_bounds__(256, 1)
void conv_mma(const float* __restrict__ in, const float* __restrict__ w,
              const float* __restrict__ cbias,
              const float* __restrict__ bng, const float* __restrict__ bnb,
              const float* __restrict__ bnm, const float* __restrict__ bnv,
              float* __restrict__ out)
{
    constexpr int K   = CIN * 9;
    constexpr int NKT = K / 16;

    extern __shared__ uint32_t sm[];
    constexpr int AS0 = 0;          // A: [128][12] half2-words
    constexpr int AS1 = 1536;
    constexpr int BS0 = 3072;       // B: [256][12] half2-words
    constexpr int BS1 = 6144;
    constexpr int TAB = 9216;       // im2col table: K ints

    const int t    = threadIdx.x;
    const int wid  = t >> 5;
    const int lane = t & 31;
    const int g    = lane >> 2;     // groupID
    const int tig  = lane & 3;      // thread-in-group
    const int warp_m = (wid >> 2) * 64;
    const int warp_n = (wid & 3) * 64;

    const int m0    = blockIdx.x * 128;
    const int pix0  = blockIdx.y * 256;
    const int bn    = pix0 >> 12;
    const int lpix0 = pix0 & 4095;

    // im2col offset table: (elem_off+65) | (tap r << 21); max 511*4096+130 < 2^21.
    for (int k = t; k < K; k += 256) {
        const int cin = k / 9;
        const int r   = k - cin * 9;
        const int dh  = r / 3 - 1;
        const int dw  = r - (r / 3) * 3 - 1;
        ((int*)(sm + TAB))[k] = ((cin * PIX + dh * HW + dw) + 65) | (r << 21);
    }
    __syncthreads();

    // B-gather: thread t owns pixel n = t (tile = 4 image rows)
    const int hh = (lpix0 >> 6) + (t >> 6);
    const int ww = t & 63;
    const float* pTh = in + (size_t)bn * CIN * PIX + hh * HW + ww;
    unsigned msk = 0;
    #pragma unroll
    for (int r = 0; r < 9; r++) {
        const int dh = r / 3 - 1, dw = r % 3 - 1;
        if ((unsigned)(hh + dh) < (unsigned)HW && (unsigned)(ww + dw) < (unsigned)HW)
            msk |= 1u << r;
    }

    // A-load: thread t owns weight row m = t>>1, k-half (t&1)*8
    const int am = t >> 1;
    const int ak = (t & 1) * 8;
    const float* wp = w + (size_t)(m0 + am) * K + ak;

    float4 rA0, rA1;
    float  rB[16];

    auto fetch = [&](int kt) {
        const int k0 = kt * 16;
        rA0 = __ldg((const float4*)(wp + k0));
        rA1 = __ldg((const float4*)(wp + k0 + 4));
        const int* tab = (const int*)(sm + TAB) + k0;
        #pragma unroll
        for (int j = 0; j < 16; j++) {
            const int e   = tab[j];
            const int r   = e >> 21;
            const int off = (e & 0x1FFFFF) - 65;
            rB[j] = ((msk >> r) & 1u) ? __ldg(pTh + off) : 0.f;
        }
    };
    auto stage = [&](int buf) {
        // A: 8 floats -> 4 half2 words -> one STS.128 at word am*12 + 4*(t&1)
        uint4 av;
        av.x = h2pack(rA0.x, rA0.y);
        av.y = h2pack(rA0.z, rA0.w);
        av.z = h2pack(rA1.x, rA1.y);
        av.w = h2pack(rA1.z, rA1.w);
        *(uint4*)(sm + (buf ? AS1 : AS0) + am * 12 + 4 * (t & 1)) = av;
        // B: 16 floats -> 8 half2 words -> two STS.128 at word t*12
        uint32_t* Bs = sm + (buf ? BS1 : BS0) + t * 12;
        uint4 b0, b1;
        b0.x = h2pack(rB[0],  rB[1]);
        b0.y = h2pack(rB[2],  rB[3]);
        b0.z = h2pack(rB[4],  rB[5]);
        b0.w = h2pack(rB[6],  rB[7]);
        b1.x = h2pack(rB[8],  rB[9]);
        b1.y = h2pack(rB[10], rB[11]);
        b1.z = h2pack(rB[12], rB[13]);
        b1.w = h2pack(rB[14], rB[15]);
        *(uint4*)(Bs)     = b0;
        *(uint4*)(Bs + 4) = b1;
    };

    float c[4][8][4];
    #pragma unroll
    for (int mf = 0; mf < 4; mf++)
        #pragma unroll
        for (int nf = 0; nf < 8; nf++)
            #pragma unroll
            for (int i = 0; i < 4; i++) c[mf][nf][i] = 0.f;

    fetch(0);
    stage(0);
    __syncthreads();

    for (int kt = 0; kt < NKT; ++kt) {
        if (kt + 1 < NKT) fetch(kt + 1);

        const uint32_t* As = sm + ((kt & 1) ? AS1 : AS0);
        const uint32_t* Bs = sm + ((kt & 1) ? BS1 : BS0);
        uint32_t a[4][4], b[8][2];
        #pragma unroll
        for (int mf = 0; mf < 4; mf++) {
            const uint32_t* ap = As + (warp_m + mf * 16 + g) * 12 + tig;
            a[mf][0] = ap[0];          // (g,      k 2tig..2tig+1)
            a[mf][1] = ap[8 * 12];     // (g+8,    k 2tig..)
            a[mf][2] = ap[4];          // (g,      k 2tig+8..)
            a[mf][3] = ap[8 * 12 + 4]; // (g+8,    k 2tig+8..)
        }
        #pragma unroll
        for (int nf = 0; nf < 8; nf++) {
            const uint32_t* bp = Bs + (warp_n + nf * 8 + g) * 12 + tig;
            b[nf][0] = bp[0];          // (k 2tig..,   n g)
            b[nf][1] = bp[4];          // (k 2tig+8.., n g)
        }
        #pragma unroll
        for (int mf = 0; mf < 4; mf++)
            #pragma unroll
            for (int nf = 0; nf < 8; nf++)
                mma_f16(c[mf][nf], a[mf], b[nf]);

        if (kt + 1 < NKT) stage((kt + 1) & 1);
        __syncthreads();
    }

    // ---- epilogue: BN + ReLU, direct to gmem (C layout same as tf32 k8) ----
    #pragma unroll
    for (int mf = 0; mf < 4; mf++) {
        const int r0  = warp_m + mf * 16 + g;
        const int oc0 = m0 + r0;
        const int oc1 = oc0 + 8;
        const float s0  = bng[oc0] * rsqrtf(bnv[oc0] + 1e-5f);
        const float sh0 = (cbias[oc0] - bnm[oc0]) * s0 + bnb[oc0];
        const float s1  = bng[oc1] * rsqrtf(bnv[oc1] + 1e-5f);
        const float sh1 = (cbias[oc1] - bnm[oc1]) * s1 + bnb[oc1];
        float* o0 = out + ((size_t)(bn * HIDC + oc0)) * PIX + lpix0;
        float* o1 = o0 + 8 * PIX;
        #pragma unroll
        for (int nf = 0; nf < 8; nf++) {
            const int col = warp_n + nf * 8 + 2 * tig;
            float2 v0, v1;
            v0.x = fmaxf(fmaf(c[mf][nf][0], s0, sh0), 0.f);
            v0.y = fmaxf(fmaf(c[mf][nf][1], s0, sh0), 0.f);
            v1.x = fmaxf(fmaf(c[mf][nf][2], s1, sh1), 0.f);
            v1.y = fmaxf(fmaf(c[mf][nf][3], s1, sh1), 0.f);
            *(float2*)(o0 + col) = v0;
            *(float2*)(o1 + col) = v1;
        }
    }
}

// ---------------- adaptive avg pool 64x64 -> 4x4 ----------------------------
__global__ void pool_kernel(float* __restrict__ feat)
{
    const int nc = blockIdx.x;
    const int n  = nc >> 9;
    const int c  = nc & 511;
    const float* p = g_act2 + (size_t)nc * PIX;
    const int t = threadIdx.x;
    const int q = t >> 4, r = t & 15;
    const int qh = q >> 2, qw = q & 3;
    const float* row = p + (qh * 16 + r) * HW + qw * 16;
    float s = 0.f;
    #pragma unroll
    for (int j = 0; j < 16; j++) s += row[j];
    __shared__ float part[256];
    part[t] = s;
    __syncthreads();
    if (t < 16) {
        float acc = 0.f;
        #pragma unroll
        for (int j = 0; j < 16; j++) acc += part[t * 16 + j];
        feat[n * FLAT + c * 16 + t] = acc * (1.f / 256.f);
    }
}

// ---------------- clinical embedding (4 -> 128) -----------------------------
__global__ void clin_kernel(const float* __restrict__ x, const float* __restrict__ w,
                            const float* __restrict__ b, float* __restrict__ feat)
{
    const int n = blockIdx.x;
    const int j = threadIdx.x;
    float s = b[j];
    #pragma unroll
    for (int i = 0; i < 4; i++) s = fmaf(w[j * 4 + i], x[n * 4 + i], s);
    feat[n * FLAT + 8192 + j] = s;
}

// ---------------- generic linear: warp per (n, o) ---------------------------
__global__ void linear_kernel(const float* __restrict__ in, const float* __restrict__ w,
                              const float* __restrict__ b, float* __restrict__ out,
                              int In, int Out, int act)
{
    const int gw   = (blockIdx.x * blockDim.x + threadIdx.x) >> 5;
    const int lane = threadIdx.x & 31;
    if (gw >= 16 * Out) return;
    const int o = gw >> 4;
    const int n = gw & 15;
    const float* wr = w + (size_t)o * In;
    const float* xr = in + (size_t)n * In;
    float s = 0.f;
    for (int i = lane; i < In; i += 32) s = fmaf(wr[i], xr[i], s);
    #pragma unroll
    for (int off = 16; off; off >>= 1) s += __shfl_xor_sync(0xFFFFFFFFu, s, off);
    if (lane == 0) {
        s += b[o];
        if (act == 1)      s = fmaxf(s, 0.f);
        else if (act == 2) s = 1.f / (1.f + expf(-s));
        else if (act == 3) s = fminf(fmaxf(s, -5.f), 0.f);
        out[n * Out + o] = s;
    }
}

// ---------------- sampling head ---------------------------------------------
__global__ void head_kernel(const float* __restrict__ noise, const float* __restrict__ u,
                            float* __restrict__ out)
{
    const int t = threadIdx.x;
    if (t >= 48) return;
    const int n = t / 3, k = t % 3;
    const int nk = n * 3 + k;
    float pm[4], ls[4], p[4];
    float lp = 0.f;
    #pragma unroll
    for (int j = 0; j < 4; j++) {
        pm[j] = g_pm[n * 12 + k * 4 + j];
        ls[j] = g_ls[n * 12 + k * 4 + j];
        const float sd = expf(ls[j]);
        p[j] = pm[j] + noise[nk * 4 + j] * sd;
        const float z = (p[j] - pm[j]) / sd;
        lp += z * z + 2.f * ls[j];
    }
    lp *= -0.5f;
    #pragma unroll
    for (int j = 0; j < 4; j++) p[j] = fminf(fmaxf(p[j], 0.f), 1.f);
    const float cx = p[0], cy = p[1];
    const float s2 = p[2] * 0.2f + 0.1f;
    const float s3 = p[3] * 0.2f + 0.1f;
    out[480 + nk] = lp;
    out[528 + nk * 4 + 0] = cx;
    out[528 + nk * 4 + 1] = cy;
    out[528 + nk * 4 + 2] = s2;
    out[528 + nk * 4 + 3] = s3;
    #pragma unroll
    for (int pt = 0; pt < 5; pt++) {
        const float ux = u[(nk * 5 + pt) * 2 + 0];
        const float uy = u[(nk * 5 + pt) * 2 + 1];
        float px = (cx + (ux - 0.5f) * s2) * 256.f;
        float py = (cy + (uy - 0.5f) * s3) * 256.f;
        px = fminf(fmaxf(px, 0.f), 255.f);
        py = fminf(fmaxf(py, 0.f), 255.f);
        out[(n * 15 + k * 5 + pt) * 2 + 0] = px;
        out[(n * 15 + k * 5 + pt) * 2 + 1] = py;
    }
}

// ---------------- launcher ---------------------------------------------------
extern "C" void kernel_launch(void* const* d_in, const int* in_sizes, int n_in,
                              void* d_out, int out_size)
{
    const float* img   = (const float*)d_in[0];
    const float* clin  = (const float*)d_in[1];
    const float* noise = (const float*)d_in[2];
    const float* u     = (const float*)d_in[3];
    const float* c1w = (const float*)d_in[4];
    const float* c1b = (const float*)d_in[5];
    const float* b1g = (const float*)d_in[6];
    const float* b1b = (const float*)d_in[7];
    const float* b1m = (const float*)d_in[8];
    const float* b1v = (const float*)d_in[9];
    const float* c2w = (const float*)d_in[10];
    const float* c2b = (const float*)d_in[11];
    const float* b2g = (const float*)d_in[12];
    const float* b2b = (const float*)d_in[13];
    const float* b2m = (const float*)d_in[14];
    const float* b2v = (const float*)d_in[15];
    const float* clw = (const float*)d_in[16];
    const float* clb = (const float*)d_in[17];
    const float* p1w = (const float*)d_in[18];
    const float* p1b = (const float*)d_in[19];
    const float* p2w = (const float*)d_in[20];
    const float* p2b = (const float*)d_in[21];
    const float* p3w = (const float*)d_in[22];
    const float* p3b = (const float*)d_in[23];
    const float* l1w = (const float*)d_in[24];
    const float* l1b = (const float*)d_in[25];
    const float* l2w = (const float*)d_in[26];
    const float* l2b = (const float*)d_in[27];

    float *act1, *act2, *feat, *h1, *h2, *g1, *pm, *ls;
    cudaGetSymbolAddress((void**)&act1, g_act1);
    cudaGetSymbolAddress((void**)&act2, g_act2);
    cudaGetSymbolAddress((void**)&feat, g_feat);
    cudaGetSymbolAddress((void**)&h1,   g_h1);
    cudaGetSymbolAddress((void**)&h2,   g_h2);
    cudaGetSymbolAddress((void**)&g1,   g_g1);
    cudaGetSymbolAddress((void**)&pm,   g_pm);
    cudaGetSymbolAddress((void**)&ls,   g_ls);

    const int smem1 = 9216 * 4 + 2304 * 4;   // 46080 B
    const int smem2 = 9216 * 4 + 4608 * 4;   // 55296 B
    cudaFuncSetAttribute(conv_mma<256>, cudaFuncAttributeMaxDynamicSharedMemorySize, smem1);
    cudaFuncSetAttribute(conv_mma<512>, cudaFuncAttributeMaxDynamicSharedMemorySize, smem2);

    const dim3 cgrid(HIDC / 128, NPIX / 256);   // (4, 256)
    conv_mma<256><<<cgrid, 256, smem1>>>(img,  c1w, c1b, b1g, b1b, b1m, b1v, act1);
    conv_mma<512><<<cgrid, 256, smem2>>>(act1, c2w, c2b, b2g, b2b, b2m, b2v, act2);

    pool_kernel<<<BATCH * HIDC, 256>>>(feat);
    clin_kernel<<<BATCH, 128>>>(clin, clw, clb, feat);

    linear_kernel<<<(16 * 512 + 7) / 8, 256>>>(feat, p1w, p1b, h1, FLAT, 512, 1);
    linear_kernel<<<(16 * 256 + 7) / 8, 256>>>(h1,   p2w, p2b, h2, 512,  256, 1);
    linear_kernel<<<(16 * 12  + 7) / 8, 256>>>(h2,   p3w, p3b, pm, 256,  12,  2);
    linear_kernel<<<(16 * 256 + 7) / 8, 256>>>(feat, l1w, l1b, g1, FLAT, 256, 1);
    linear_kernel<<<(16 * 12  + 7) / 8, 256>>>(g1,   l2w, l2b, ls, 256,  12,  3);

    head_kernel<<<1, 64>>>(noise, u, (float*)d_out);
}